// round 12
// baseline (speedup 1.0000x reference)
#include <cuda_runtime.h>

#define S_ 160
#define H_ 768

// scratch (device globals — no allocation allowed)
__device__ float g_yrot[S_ * H_];
__device__ float g_L[S_ * H_];
__device__ float g_R[S_ * H_];

typedef unsigned long long u64;

__device__ __forceinline__ void fma2(u64& d, u64 a, u64 b) {
    asm volatile("fma.rn.f32x2 %0, %1, %2, %0;" : "+l"(d) : "l"(a), "l"(b));
}
__device__ __forceinline__ u64 pack2(float x, float y) {
    u64 r; asm("mov.b64 %0, {%1, %2};" : "=l"(r) : "f"(x), "f"(y)); return r;
}
__device__ __forceinline__ float2 unpack2(u64 v) {
    float2 f; asm("mov.b64 {%0, %1}, %2;" : "=f"(f.x), "=f"(f.y) : "l"(v)); return f;
}
__device__ __forceinline__ float sigf(float x) { return 1.0f / (1.0f + __expf(-x)); }

__device__ __forceinline__ float4 reluadd4(float4 a, float4 b) {
    float4 r;
    r.x = fmaxf(a.x + b.x, 0.f);
    r.y = fmaxf(a.y + b.y, 0.f);
    r.z = fmaxf(a.z + b.z, 0.f);
    r.w = fmaxf(a.w + b.w, 0.f);
    return r;
}

// ---------------------------------------------------------------------------
// Kernel A: RoPE.  grid 160, block 384
// ---------------------------------------------------------------------------
__global__ void rope_kernel(const float* __restrict__ y) {
    int s = blockIdx.x;
    int k = threadIdx.x;  // 0..383
    float inv = expf(-(2.0f * (float)k / 768.0f) * 9.210340371976184f);
    float th = (float)s * inv;
    float sn, cs;
    sincosf(th, &sn, &cs);
    float y0 = y[s * H_ + 2 * k];
    float y1 = y[s * H_ + 2 * k + 1];
    g_yrot[s * H_ + 2 * k]     = y0 * cs - y1 * sn;
    g_yrot[s * H_ + 2 * k + 1] = y1 * cs + y0 * sn;
}

// ---------------------------------------------------------------------------
// Kernel B: L/R projections.  BM=32, BN=64, BK=16.  grid (5, 24), 256 thr.
// (R6/R10-proven.)
// ---------------------------------------------------------------------------
__global__ __launch_bounds__(256) void lr_kernel(const float* __restrict__ W1,
                                                 const float* __restrict__ b1) {
    __shared__ float As[16][34];
    __shared__ float Bs[16][68];

    int t = threadIdx.x;
    int Mtile = blockIdx.x;
    int nbase = blockIdx.y * 64;
    int isR = (nbase >= 768);
    int obase = isR ? (nbase - 768) : nbase;
    int cofs = isR ? 768 : 0;
    int tx = t & 15, ty = t >> 4;

    float acc[2][4];
#pragma unroll
    for (int r = 0; r < 2; r++)
#pragma unroll
        for (int c = 0; c < 4; c++) acc[r][c] = 0.f;

    for (int k0 = 0; k0 < H_; k0 += 16) {
#pragma unroll
        for (int it = 0; it < 2; it++) {
            int q = t + it * 256;
            int row = q >> 4, kk = q & 15;
            As[kk][row] = g_yrot[(Mtile * 32 + row) * H_ + k0 + kk];
        }
#pragma unroll
        for (int it = 0; it < 4; it++) {
            int q = t + it * 256;
            int nn = q >> 4, kk = q & 15;
            Bs[kk][nn] = W1[(obase + nn) * 1536 + cofs + k0 + kk];
        }
        __syncthreads();
#pragma unroll
        for (int kk = 0; kk < 16; kk++) {
            float a0 = As[kk][ty * 2 + 0];
            float a1 = As[kk][ty * 2 + 1];
            float4 b = *(const float4*)&Bs[kk][tx * 4];
            acc[0][0] += a0 * b.x; acc[0][1] += a0 * b.y;
            acc[0][2] += a0 * b.z; acc[0][3] += a0 * b.w;
            acc[1][0] += a1 * b.x; acc[1][1] += a1 * b.y;
            acc[1][2] += a1 * b.z; acc[1][3] += a1 * b.w;
        }
        __syncthreads();
    }

    int s0 = Mtile * 32 + ty * 2;
#pragma unroll
    for (int c = 0; c < 4; c++) {
        int o = obase + tx * 4 + c;
        if (isR) {
            float bb = b1[o];
            g_R[(s0 + 0) * H_ + o] = acc[0][c] + bb;
            g_R[(s0 + 1) * H_ + o] = acc[1][c] + bb;
        } else {
            g_L[(s0 + 0) * H_ + o] = acc[0][c];
            g_L[(s0 + 1) * H_ + o] = acc[1][c];
        }
    }
}

// ---------------------------------------------------------------------------
// Kernel C: main GEMM, occupancy-3 variant.
//   BM=128, BN=64, BK=16, 256 thr, 8x4 microtile (f32x2 FMA), grid (200, 4).
//   acc 16 u64 + A 4 u64 + bD 4 u64 + 12 prefetch -> ~80 regs, 3 CTAs/SM.
// ---------------------------------------------------------------------------
__global__ __launch_bounds__(256, 3) void main_kernel(const float* __restrict__ W2,
                                                      const float* __restrict__ b2,
                                                      float* __restrict__ out) {
    __shared__ __align__(16) float As[16][132];  // [k][pair-row], padded
    __shared__ __align__(16) float Bs[16][68];   // [k][o-col], padded

    int t = threadIdx.x;
    int Mtile = blockIdx.x;   // 0..199
    int Ntile = blockIdx.y;   // 0..3
    int tx = t & 15, ty = t >> 4;   // col group (4 cols), row group (8 rows)

    int rowA = t >> 2;        // 0..63
    int segOff = (t & 3) * 4; // 0,4,8,12

    int p0 = Mtile * 128 + rowA;
    int p1 = p0 + 64;
    int i0 = p0 / 160, j0 = p0 - i0 * 160;
    int i1 = p1 / 160, j1 = p1 - i1 * 160;
    const float* Lp0 = g_L + i0 * H_;
    const float* Rp0 = g_R + j0 * H_;
    const float* Lp1 = g_L + i1 * H_;
    const float* Rp1 = g_R + j1 * H_;
    const float* Wp = W2 + (Ntile * 64 + rowA) * H_;

    u64 acc[4][4];
#pragma unroll
    for (int r = 0; r < 4; r++)
#pragma unroll
        for (int c = 0; c < 4; c++) acc[r][c] = 0ULL;

    // prefetch chunk 0
    float4 aP0 = reluadd4(*(const float4*)(Lp0 + segOff), *(const float4*)(Rp0 + segOff));
    float4 aP1 = reluadd4(*(const float4*)(Lp1 + segOff), *(const float4*)(Rp1 + segOff));
    float4 bP = *(const float4*)(Wp + segOff);

    for (int k0 = 0; k0 < H_; k0 += 16) {
        // stage current chunk to smem
        As[segOff + 0][rowA] = aP0.x; As[segOff + 1][rowA] = aP0.y;
        As[segOff + 2][rowA] = aP0.z; As[segOff + 3][rowA] = aP0.w;
        As[segOff + 0][rowA + 64] = aP1.x; As[segOff + 1][rowA + 64] = aP1.y;
        As[segOff + 2][rowA + 64] = aP1.z; As[segOff + 3][rowA + 64] = aP1.w;
        Bs[segOff + 0][rowA] = bP.x; Bs[segOff + 1][rowA] = bP.y;
        Bs[segOff + 2][rowA] = bP.z; Bs[segOff + 3][rowA] = bP.w;
        __syncthreads();

        // prefetch next chunk while computing
        int kn = k0 + 16;
        if (kn < H_) {
            aP0 = reluadd4(*(const float4*)(Lp0 + kn + segOff), *(const float4*)(Rp0 + kn + segOff));
            aP1 = reluadd4(*(const float4*)(Lp1 + kn + segOff), *(const float4*)(Rp1 + kn + segOff));
            bP = *(const float4*)(Wp + kn + segOff);
        }

#pragma unroll
        for (int kk = 0; kk < 16; kk++) {
            ulonglong2 av0 = *(const ulonglong2*)&As[kk][ty * 8];
            ulonglong2 av1 = *(const ulonglong2*)&As[kk][ty * 8 + 4];
            float4 bf = *(const float4*)&Bs[kk][tx * 4];
            u64 a2[4] = {av0.x, av0.y, av1.x, av1.y};
            u64 bD[4];
            bD[0] = pack2(bf.x, bf.x); bD[1] = pack2(bf.y, bf.y);
            bD[2] = pack2(bf.z, bf.z); bD[3] = pack2(bf.w, bf.w);
#pragma unroll
            for (int rp = 0; rp < 4; rp++)
#pragma unroll
                for (int c = 0; c < 4; c++)
                    fma2(acc[rp][c], a2[rp], bD[c]);
        }
        __syncthreads();
    }

    // epilogue: +b2, sigmoid, scatter into (65,160,160,4) layout
    int ob = Ntile * 64 + tx * 4;    // multiple of 4
    float4 bias = *(const float4*)&b2[ob];
    int rI = ob >> 2;                // rel index

#pragma unroll
    for (int rp = 0; rp < 4; rp++) {
        float2 v0 = unpack2(acc[rp][0]);
        float2 v1 = unpack2(acc[rp][1]);
        float2 v2 = unpack2(acc[rp][2]);
        float2 v3 = unpack2(acc[rp][3]);
#pragma unroll
        for (int h = 0; h < 2; h++) {
            int r = ty * 8 + rp * 2 + h;
            int p = Mtile * 128 + r;
            int i = p / 160, j = p - i * 160;
            float4 o;
            o.x = sigf((h ? v0.y : v0.x) + bias.x);
            o.y = sigf((h ? v1.y : v1.x) + bias.y);
            o.z = sigf((h ? v2.y : v2.x) + bias.z);
            o.w = sigf((h ? v3.y : v3.x) + bias.w);
            *(float4*)&out[((rI * 160 + i) * 160 + j) * 4] = o;
        }
    }
}

// ---------------------------------------------------------------------------
// Kernel D: tail outputs o = 256..259 (rel index 64).  grid 100, block 256.
// (R10-proven.)
// ---------------------------------------------------------------------------
__global__ __launch_bounds__(256) void tail_kernel(const float* __restrict__ W2,
                                                   const float* __restrict__ b2,
                                                   float* __restrict__ out) {
    __shared__ float W2s[4 * H_];
    __shared__ float Ls[3 * H_];

    int t = threadIdx.x;
    int bt = blockIdx.x;             // 0..99
    int p0 = bt * 256;
    int ibase = p0 / 160;

    for (int q = t; q < 4 * H_; q += 256) W2s[q] = W2[256 * H_ + q];
    for (int q = t; q < 3 * H_; q += 256) {
        int r = q / H_;
        int ri = ibase + r; if (ri > 159) ri = 159;
        Ls[q] = g_L[ri * H_ + (q - r * H_)];
    }
    __syncthreads();

    int p = p0 + t;
    int i = p / 160, j = p - i * 160;
    const float4* Rr = (const float4*)(g_R + j * H_);
    const float4* Lr = (const float4*)(Ls + (i - ibase) * H_);
    const float4* w0 = (const float4*)(W2s);
    const float4* w1 = (const float4*)(W2s + H_);
    const float4* w2 = (const float4*)(W2s + 2 * H_);
    const float4* w3 = (const float4*)(W2s + 3 * H_);

    float a0 = 0.f, a1 = 0.f, a2 = 0.f, a3 = 0.f;
#pragma unroll 4
    for (int kk = 0; kk < H_ / 4; kk++) {
        float4 l = Lr[kk];
        float4 r4 = Rr[kk];
        float4 hh = reluadd4(l, r4);
        float4 q0 = w0[kk], q1 = w1[kk], q2 = w2[kk], q3 = w3[kk];
        a0 = fmaf(hh.x, q0.x, fmaf(hh.y, q0.y, fmaf(hh.z, q0.z, fmaf(hh.w, q0.w, a0))));
        a1 = fmaf(hh.x, q1.x, fmaf(hh.y, q1.y, fmaf(hh.z, q1.z, fmaf(hh.w, q1.w, a1))));
        a2 = fmaf(hh.x, q2.x, fmaf(hh.y, q2.y, fmaf(hh.z, q2.z, fmaf(hh.w, q2.w, a2))));
        a3 = fmaf(hh.x, q3.x, fmaf(hh.y, q3.y, fmaf(hh.z, q3.z, fmaf(hh.w, q3.w, a3))));
    }
    float4 o;
    o.x = sigf(a0 + b2[256]);
    o.y = sigf(a1 + b2[257]);
    o.z = sigf(a2 + b2[258]);
    o.w = sigf(a3 + b2[259]);
    *(float4*)&out[((64 * 160 + i) * 160 + j) * 4] = o;
}

// ---------------------------------------------------------------------------
extern "C" void kernel_launch(void* const* d_in, const int* in_sizes, int n_in,
                              void* d_out, int out_size) {
    const float* y  = (const float*)d_in[0];
    // d_in[1] = event_idx (unused by reference)
    const float* W1 = (const float*)d_in[2];
    const float* b1 = (const float*)d_in[3];
    const float* W2 = (const float*)d_in[4];
    const float* b2 = (const float*)d_in[5];
    float* out = (float*)d_out;

    rope_kernel<<<160, 384>>>(y);
    lr_kernel<<<dim3(5, 24), 256>>>(W1, b1);
    tail_kernel<<<100, 256>>>(W2, b2, out);
    main_kernel<<<dim3(200, 4), 256>>>(W2, b2, out);
}

// round 14
// speedup vs baseline: 2.2943x; 2.2943x over previous
#include <cuda_runtime.h>
#include <cstdint>

#define S_ 160
#define H_ 768

// scratch (device globals — no allocation allowed)
__device__ float g_yrot[S_ * H_];
__device__ float g_L[S_ * H_];
__device__ float g_R[S_ * H_];

__device__ __forceinline__ float sigf(float x) { return 1.0f / (1.0f + __expf(-x)); }

__device__ __forceinline__ float4 reluadd4(float4 a, float4 b) {
    float4 r;
    r.x = fmaxf(a.x + b.x, 0.f);
    r.y = fmaxf(a.y + b.y, 0.f);
    r.z = fmaxf(a.z + b.z, 0.f);
    r.w = fmaxf(a.w + b.w, 0.f);
    return r;
}

__device__ __forceinline__ uint32_t tf32b(float x) {
    uint32_t r;
    asm("cvt.rna.tf32.f32 %0, %1;" : "=r"(r) : "f"(x));
    return r;
}

// D += A(16x8) * B(8x8), tf32 in, fp32 accum.  Canonical m16n8k8 fragments.
__device__ __forceinline__ void mma_tf32(float* c,
                                         uint32_t a0, uint32_t a1, uint32_t a2, uint32_t a3,
                                         uint32_t b0, uint32_t b1) {
    asm volatile(
        "mma.sync.aligned.m16n8k8.row.col.f32.tf32.tf32.f32 "
        "{%0,%1,%2,%3}, {%4,%5,%6,%7}, {%8,%9}, {%0,%1,%2,%3};"
        : "+f"(c[0]), "+f"(c[1]), "+f"(c[2]), "+f"(c[3])
        : "r"(a0), "r"(a1), "r"(a2), "r"(a3), "r"(b0), "r"(b1));
}

// ---------------------------------------------------------------------------
// Kernel A: RoPE.  grid 160, block 384
// ---------------------------------------------------------------------------
__global__ void rope_kernel(const float* __restrict__ y) {
    int s = blockIdx.x;
    int k = threadIdx.x;  // 0..383
    float inv = expf(-(2.0f * (float)k / 768.0f) * 9.210340371976184f);
    float th = (float)s * inv;
    float sn, cs;
    sincosf(th, &sn, &cs);
    float y0 = y[s * H_ + 2 * k];
    float y1 = y[s * H_ + 2 * k + 1];
    g_yrot[s * H_ + 2 * k]     = y0 * cs - y1 * sn;
    g_yrot[s * H_ + 2 * k + 1] = y1 * cs + y0 * sn;
}

// ---------------------------------------------------------------------------
// Kernel B: L/R projections.  BM=32, BN=64, BK=16.  grid (5, 24), 256 thr.
// (R10-proven.)
// ---------------------------------------------------------------------------
__global__ __launch_bounds__(256) void lr_kernel(const float* __restrict__ W1,
                                                 const float* __restrict__ b1) {
    __shared__ float As[16][34];
    __shared__ float Bs[16][68];

    int t = threadIdx.x;
    int Mtile = blockIdx.x;
    int nbase = blockIdx.y * 64;
    int isR = (nbase >= 768);
    int obase = isR ? (nbase - 768) : nbase;
    int cofs = isR ? 768 : 0;
    int tx = t & 15, ty = t >> 4;

    float acc[2][4];
#pragma unroll
    for (int r = 0; r < 2; r++)
#pragma unroll
        for (int c = 0; c < 4; c++) acc[r][c] = 0.f;

    for (int k0 = 0; k0 < H_; k0 += 16) {
#pragma unroll
        for (int it = 0; it < 2; it++) {
            int q = t + it * 256;
            int row = q >> 4, kk = q & 15;
            As[kk][row] = g_yrot[(Mtile * 32 + row) * H_ + k0 + kk];
        }
#pragma unroll
        for (int it = 0; it < 4; it++) {
            int q = t + it * 256;
            int nn = q >> 4, kk = q & 15;
            Bs[kk][nn] = W1[(obase + nn) * 1536 + cofs + k0 + kk];
        }
        __syncthreads();
#pragma unroll
        for (int kk = 0; kk < 16; kk++) {
            float a0 = As[kk][ty * 2 + 0];
            float a1 = As[kk][ty * 2 + 1];
            float4 b = *(const float4*)&Bs[kk][tx * 4];
            acc[0][0] += a0 * b.x; acc[0][1] += a0 * b.y;
            acc[0][2] += a0 * b.z; acc[0][3] += a0 * b.w;
            acc[1][0] += a1 * b.x; acc[1][1] += a1 * b.y;
            acc[1][2] += a1 * b.z; acc[1][3] += a1 * b.w;
        }
        __syncthreads();
    }

    int s0 = Mtile * 32 + ty * 2;
#pragma unroll
    for (int c = 0; c < 4; c++) {
        int o = obase + tx * 4 + c;
        if (isR) {
            float bb = b1[o];
            g_R[(s0 + 0) * H_ + o] = acc[0][c] + bb;
            g_R[(s0 + 1) * H_ + o] = acc[1][c] + bb;
        } else {
            g_L[(s0 + 0) * H_ + o] = acc[0][c];
            g_L[(s0 + 1) * H_ + o] = acc[1][c];
        }
    }
}

// ---------------------------------------------------------------------------
// Kernel C: main GEMM on tensor cores via mma.sync tf32 (m16n8k8).
//   out[p,o] = sigmoid(sum_h relu(L[i,h]+R[j,h]) * W2[o,h] + b2[o]).
//   BM=128, BN=128, BK=16, 256 thr (8 warps: 4 row-groups x 2 col-groups),
//   warp tile 32x64 (2 m16 x 8 n8), grid (200, 2).
//   As/Bs stored [k][m-or-n] with pad 136 -> conflict-free fragment loads.
// ---------------------------------------------------------------------------
__global__ __launch_bounds__(256, 2) void main_kernel(const float* __restrict__ W2,
                                                      const float* __restrict__ b2,
                                                      float* __restrict__ out) {
    __shared__ uint32_t As[16][136];   // tf32 bits of relu(L+R), [k][pair-row]
    __shared__ uint32_t Bs[16][136];   // tf32 bits of W2, [k][o-col]

    int t = threadIdx.x;
    int Mtile = blockIdx.x;   // 0..199
    int Ntile = blockIdx.y;   // 0..1
    int lane = t & 31, wid = t >> 5;
    int wy = wid >> 1;        // 0..3 : rows wy*32 .. +31
    int wx = wid & 1;         // 0..1 : cols wx*64 .. +63
    int g = lane >> 2, tig = lane & 3;

    // staging mapping (R1): thread owns rows rowA, rowA+64; k-span segOff..+3
    int rowA = t >> 2;        // 0..63
    int seg = t & 3;
    int segOff = seg * 4;

    int p0 = Mtile * 128 + rowA;
    int p1 = p0 + 64;
    int i0 = p0 / 160, j0 = p0 - i0 * 160;
    int i1 = p1 / 160, j1 = p1 - i1 * 160;
    const float* Lp0 = g_L + i0 * H_;
    const float* Rp0 = g_R + j0 * H_;
    const float* Lp1 = g_L + i1 * H_;
    const float* Rp1 = g_R + j1 * H_;
    const float* Wp0 = W2 + (Ntile * 128 + rowA) * H_;
    const float* Wp1 = Wp0 + 64 * H_;

    float acc[2][8][4];
#pragma unroll
    for (int m = 0; m < 2; m++)
#pragma unroll
        for (int nt = 0; nt < 8; nt++)
#pragma unroll
            for (int c = 0; c < 4; c++) acc[m][nt][c] = 0.f;

    // prefetch chunk 0
    float4 aP0 = reluadd4(*(const float4*)(Lp0 + segOff), *(const float4*)(Rp0 + segOff));
    float4 aP1 = reluadd4(*(const float4*)(Lp1 + segOff), *(const float4*)(Rp1 + segOff));
    float4 bP0 = *(const float4*)(Wp0 + segOff);
    float4 bP1 = *(const float4*)(Wp1 + segOff);

    for (int k0 = 0; k0 < H_; k0 += 16) {
        // stage current chunk (tf32-rounded); e-order rotated by seg so the four
        // seg groups hit different bank sets each step (avoids 4-way STS conflict)
        float a0v[4] = {aP0.x, aP0.y, aP0.z, aP0.w};
        float a1v[4] = {aP1.x, aP1.y, aP1.z, aP1.w};
        float b0v[4] = {bP0.x, bP0.y, bP0.z, bP0.w};
        float b1v[4] = {bP1.x, bP1.y, bP1.z, bP1.w};
#pragma unroll
        for (int ep = 0; ep < 4; ep++) {
            int e = (ep + seg) & 3;
            As[segOff + e][rowA]      = tf32b(a0v[e]);
            As[segOff + e][rowA + 64] = tf32b(a1v[e]);
            Bs[segOff + e][rowA]      = tf32b(b0v[e]);
            Bs[segOff + e][rowA + 64] = tf32b(b1v[e]);
        }
        __syncthreads();

        // prefetch next chunk while computing
        int kn = k0 + 16;
        if (kn < H_) {
            aP0 = reluadd4(*(const float4*)(Lp0 + kn + segOff), *(const float4*)(Rp0 + kn + segOff));
            aP1 = reluadd4(*(const float4*)(Lp1 + kn + segOff), *(const float4*)(Rp1 + kn + segOff));
            bP0 = *(const float4*)(Wp0 + kn + segOff);
            bP1 = *(const float4*)(Wp1 + kn + segOff);
        }

#pragma unroll
        for (int q = 0; q < 2; q++) {
            int kb = q * 8;
            // load all B fragments for this k8 (cols wx*64 + nt*8 + g)
            uint32_t bf[8][2];
#pragma unroll
            for (int nt = 0; nt < 8; nt++) {
                int col = wx * 64 + nt * 8 + g;
                bf[nt][0] = Bs[kb + tig][col];
                bf[nt][1] = Bs[kb + tig + 4][col];
            }
#pragma unroll
            for (int m = 0; m < 2; m++) {
                int r0 = wy * 32 + m * 16 + g;
                uint32_t a0 = As[kb + tig][r0];
                uint32_t a1 = As[kb + tig][r0 + 8];
                uint32_t a2 = As[kb + tig + 4][r0];
                uint32_t a3 = As[kb + tig + 4][r0 + 8];
#pragma unroll
                for (int nt = 0; nt < 8; nt++)
                    mma_tf32(acc[m][nt], a0, a1, a2, a3, bf[nt][0], bf[nt][1]);
            }
        }
        __syncthreads();
    }

    // epilogue: +b2, sigmoid, scatter into (65,160,160,4) layout.
    // c0=(g, tig*2) c1=(g, tig*2+1) c2=(g+8, tig*2) c3=(g+8, tig*2+1)
#pragma unroll
    for (int m = 0; m < 2; m++) {
        int pa = Mtile * 128 + wy * 32 + m * 16 + g;
        int pb = pa + 8;
        int ia = pa / 160, ja = pa - ia * 160;
        int ib = pb / 160, jb = pb - ib * 160;
#pragma unroll
        for (int nt = 0; nt < 8; nt++) {
            int o = Ntile * 128 + wx * 64 + nt * 8 + tig * 2;
            float bx = b2[o], by = b2[o + 1];
            int rI = o >> 2;
            int off = o & 3;   // 0 or 2
            float2 va, vb;
            va.x = sigf(acc[m][nt][0] + bx);
            va.y = sigf(acc[m][nt][1] + by);
            vb.x = sigf(acc[m][nt][2] + bx);
            vb.y = sigf(acc[m][nt][3] + by);
            *(float2*)&out[((rI * 160 + ia) * 160 + ja) * 4 + off] = va;
            *(float2*)&out[((rI * 160 + ib) * 160 + jb) * 4 + off] = vb;
        }
    }
}

// ---------------------------------------------------------------------------
// Kernel D: tail outputs o = 256..259 (rel index 64).  grid 100, block 256.
// (R10-proven.)
// ---------------------------------------------------------------------------
__global__ __launch_bounds__(256) void tail_kernel(const float* __restrict__ W2,
                                                   const float* __restrict__ b2,
                                                   float* __restrict__ out) {
    __shared__ float W2s[4 * H_];
    __shared__ float Ls[3 * H_];

    int t = threadIdx.x;
    int bt = blockIdx.x;             // 0..99
    int p0 = bt * 256;
    int ibase = p0 / 160;

    for (int q = t; q < 4 * H_; q += 256) W2s[q] = W2[256 * H_ + q];
    for (int q = t; q < 3 * H_; q += 256) {
        int r = q / H_;
        int ri = ibase + r; if (ri > 159) ri = 159;
        Ls[q] = g_L[ri * H_ + (q - r * H_)];
    }
    __syncthreads();

    int p = p0 + t;
    int i = p / 160, j = p - i * 160;
    const float4* Rr = (const float4*)(g_R + j * H_);
    const float4* Lr = (const float4*)(Ls + (i - ibase) * H_);
    const float4* w0 = (const float4*)(W2s);
    const float4* w1 = (const float4*)(W2s + H_);
    const float4* w2 = (const float4*)(W2s + 2 * H_);
    const float4* w3 = (const float4*)(W2s + 3 * H_);

    float a0 = 0.f, a1 = 0.f, a2 = 0.f, a3 = 0.f;
#pragma unroll 4
    for (int kk = 0; kk < H_ / 4; kk++) {
        float4 l = Lr[kk];
        float4 r4 = Rr[kk];
        float4 hh = reluadd4(l, r4);
        float4 q0 = w0[kk], q1 = w1[kk], q2 = w2[kk], q3 = w3[kk];
        a0 = fmaf(hh.x, q0.x, fmaf(hh.y, q0.y, fmaf(hh.z, q0.z, fmaf(hh.w, q0.w, a0))));
        a1 = fmaf(hh.x, q1.x, fmaf(hh.y, q1.y, fmaf(hh.z, q1.z, fmaf(hh.w, q1.w, a1))));
        a2 = fmaf(hh.x, q2.x, fmaf(hh.y, q2.y, fmaf(hh.z, q2.z, fmaf(hh.w, q2.w, a2))));
        a3 = fmaf(hh.x, q3.x, fmaf(hh.y, q3.y, fmaf(hh.z, q3.z, fmaf(hh.w, q3.w, a3))));
    }
    float4 o;
    o.x = sigf(a0 + b2[256]);
    o.y = sigf(a1 + b2[257]);
    o.z = sigf(a2 + b2[258]);
    o.w = sigf(a3 + b2[259]);
    *(float4*)&out[((64 * 160 + i) * 160 + j) * 4] = o;
}

// ---------------------------------------------------------------------------
extern "C" void kernel_launch(void* const* d_in, const int* in_sizes, int n_in,
                              void* d_out, int out_size) {
    const float* y  = (const float*)d_in[0];
    // d_in[1] = event_idx (unused by reference)
    const float* W1 = (const float*)d_in[2];
    const float* b1 = (const float*)d_in[3];
    const float* W2 = (const float*)d_in[4];
    const float* b2 = (const float*)d_in[5];
    float* out = (float*)d_out;

    rope_kernel<<<160, 384>>>(y);
    lr_kernel<<<dim3(5, 24), 256>>>(W1, b1);
    tail_kernel<<<100, 256>>>(W2, b2, out);
    main_kernel<<<dim3(200, 2), 256>>>(W2, b2, out);
}

// round 15
// speedup vs baseline: 2.6168x; 1.1406x over previous
#include <cuda_runtime.h>
#include <cstdint>

#define S_ 160
#define H_ 768

// scratch (device globals — no allocation allowed)
__device__ float g_yrot[S_ * H_];
__device__ float g_L[S_ * H_];
__device__ float g_R[S_ * H_];

__device__ __forceinline__ float sigf(float x) { return 1.0f / (1.0f + __expf(-x)); }

__device__ __forceinline__ float4 reluadd4(float4 a, float4 b) {
    float4 r;
    r.x = fmaxf(a.x + b.x, 0.f);
    r.y = fmaxf(a.y + b.y, 0.f);
    r.z = fmaxf(a.z + b.z, 0.f);
    r.w = fmaxf(a.w + b.w, 0.f);
    return r;
}

__device__ __forceinline__ uint32_t tf32b(float x) {
    uint32_t r;
    asm("cvt.rna.tf32.f32 %0, %1;" : "=r"(r) : "f"(x));
    return r;
}

__device__ __forceinline__ uint32_t smem_u32(const void* p) {
    uint32_t a;
    asm("{ .reg .u64 t; cvta.to.shared.u64 t, %1; cvt.u32.u64 %0, t; }" : "=r"(a) : "l"(p));
    return a;
}

__device__ __forceinline__ void cp16(uint32_t dst, const void* src) {
    asm volatile("cp.async.cg.shared.global [%0], [%1], 16;" :: "r"(dst), "l"(src));
}
#define CP_COMMIT() asm volatile("cp.async.commit_group;" ::: "memory")
#define CP_WAIT0()  asm volatile("cp.async.wait_group 0;" ::: "memory")

// D += A(16x8) * B(8x8), tf32 in, fp32 accum.  Canonical m16n8k8 fragments.
__device__ __forceinline__ void mma_tf32(float* c,
                                         uint32_t a0, uint32_t a1, uint32_t a2, uint32_t a3,
                                         uint32_t b0, uint32_t b1) {
    asm volatile(
        "mma.sync.aligned.m16n8k8.row.col.f32.tf32.tf32.f32 "
        "{%0,%1,%2,%3}, {%4,%5,%6,%7}, {%8,%9}, {%0,%1,%2,%3};"
        : "+f"(c[0]), "+f"(c[1]), "+f"(c[2]), "+f"(c[3])
        : "r"(a0), "r"(a1), "r"(a2), "r"(a3), "r"(b0), "r"(b1));
}

// ---------------------------------------------------------------------------
// Kernel A: RoPE.  grid 160, block 384
// ---------------------------------------------------------------------------
__global__ void rope_kernel(const float* __restrict__ y) {
    int s = blockIdx.x;
    int k = threadIdx.x;  // 0..383
    float inv = expf(-(2.0f * (float)k / 768.0f) * 9.210340371976184f);
    float th = (float)s * inv;
    float sn, cs;
    sincosf(th, &sn, &cs);
    float y0 = y[s * H_ + 2 * k];
    float y1 = y[s * H_ + 2 * k + 1];
    g_yrot[s * H_ + 2 * k]     = y0 * cs - y1 * sn;
    g_yrot[s * H_ + 2 * k + 1] = y1 * cs + y0 * sn;
}

// ---------------------------------------------------------------------------
// Kernel B: L/R projections.  BM=32, BN=64, BK=16.  grid (5, 24), 256 thr.
// (R10-proven, verbatim.)
// ---------------------------------------------------------------------------
__global__ __launch_bounds__(256) void lr_kernel(const float* __restrict__ W1,
                                                 const float* __restrict__ b1) {
    __shared__ float As[16][34];
    __shared__ float Bs[16][68];

    int t = threadIdx.x;
    int Mtile = blockIdx.x;
    int nbase = blockIdx.y * 64;
    int isR = (nbase >= 768);
    int obase = isR ? (nbase - 768) : nbase;
    int cofs = isR ? 768 : 0;
    int tx = t & 15, ty = t >> 4;

    float acc[2][4];
#pragma unroll
    for (int r = 0; r < 2; r++)
#pragma unroll
        for (int c = 0; c < 4; c++) acc[r][c] = 0.f;

    for (int k0 = 0; k0 < H_; k0 += 16) {
#pragma unroll
        for (int it = 0; it < 2; it++) {
            int q = t + it * 256;
            int row = q >> 4, kk = q & 15;
            As[kk][row] = g_yrot[(Mtile * 32 + row) * H_ + k0 + kk];
        }
#pragma unroll
        for (int it = 0; it < 4; it++) {
            int q = t + it * 256;
            int nn = q >> 4, kk = q & 15;
            Bs[kk][nn] = W1[(obase + nn) * 1536 + cofs + k0 + kk];
        }
        __syncthreads();
#pragma unroll
        for (int kk = 0; kk < 16; kk++) {
            float a0 = As[kk][ty * 2 + 0];
            float a1 = As[kk][ty * 2 + 1];
            float4 b = *(const float4*)&Bs[kk][tx * 4];
            acc[0][0] += a0 * b.x; acc[0][1] += a0 * b.y;
            acc[0][2] += a0 * b.z; acc[0][3] += a0 * b.w;
            acc[1][0] += a1 * b.x; acc[1][1] += a1 * b.y;
            acc[1][2] += a1 * b.z; acc[1][3] += a1 * b.w;
        }
        __syncthreads();
    }

    int s0 = Mtile * 32 + ty * 2;
#pragma unroll
    for (int c = 0; c < 4; c++) {
        int o = obase + tx * 4 + c;
        if (isR) {
            float bb = b1[o];
            g_R[(s0 + 0) * H_ + o] = acc[0][c] + bb;
            g_R[(s0 + 1) * H_ + o] = acc[1][c] + bb;
        } else {
            g_L[(s0 + 0) * H_ + o] = acc[0][c];
            g_L[(s0 + 1) * H_ + o] = acc[1][c];
        }
    }
}

// ---------------------------------------------------------------------------
// Kernel C: main GEMM on tensor cores (mma.sync m16n8k8 tf32), pipelined.
//   BM=128, BN=128, BK=16, 256 thr, warp tile 32x64, grid (200, 2).
//   Double-buffered smem, ONE barrier per K-stage, B tile via cp.async
//   (raw fp32 bits -> tf32 truncation), A tile staged with cvt.rna.
//   As: [buf][k][136]  (frag loads conflict-free: bank = 8*tig + g)
//   Bs: [buf][row][20] (frag loads conflict-free: bank = 20*g + tig + kb)
// ---------------------------------------------------------------------------
__global__ __launch_bounds__(256, 2) void main_kernel(const float* __restrict__ W2,
                                                      const float* __restrict__ b2,
                                                      float* __restrict__ out) {
    __shared__ __align__(16) uint32_t As[2][16][136];
    __shared__ __align__(16) uint32_t Bs[2][128][20];

    int t = threadIdx.x;
    int Mtile = blockIdx.x;   // 0..199
    int Ntile = blockIdx.y;   // 0..1
    int lane = t & 31, wid = t >> 5;
    int wy = wid >> 1;        // 0..3 : rows wy*32 .. +31
    int wx = wid & 1;         // 0..1 : cols wx*64 .. +63
    int g = lane >> 2, tig = lane & 3;

    // A staging mapping (R14-proven): rows rowA, rowA+64; k-span segOff..+3
    int rowA = t >> 2;        // 0..63
    int seg = t & 3;
    int segOff = seg * 4;

    int p0 = Mtile * 128 + rowA;
    int p1 = p0 + 64;
    int i0 = p0 / 160, j0 = p0 - i0 * 160;
    int i1 = p1 / 160, j1 = p1 - i1 * 160;
    const float* Lp0 = g_L + i0 * H_;
    const float* Rp0 = g_R + j0 * H_;
    const float* Lp1 = g_L + i1 * H_;
    const float* Rp1 = g_R + j1 * H_;

    // B staging mapping (cp.async): row browB, 8 floats at halfB*8
    int browB = t >> 1;       // 0..127
    int halfB = t & 1;
    const float* WpB = W2 + (Ntile * 128 + browB) * H_ + halfB * 8;
    uint32_t bDst0 = smem_u32(&Bs[0][browB][halfB * 8]);
    uint32_t bDst1 = bDst0 + 128 * 20 * 4;

    float acc[2][8][4];
#pragma unroll
    for (int m = 0; m < 2; m++)
#pragma unroll
        for (int nt = 0; nt < 8; nt++)
#pragma unroll
            for (int c = 0; c < 4; c++) acc[m][nt][c] = 0.f;

    // prologue: B(0) via cp.async, A(0) into regs
    cp16(bDst0, WpB);
    cp16(bDst0 + 16, WpB + 4);
    CP_COMMIT();
    float4 aP0 = reluadd4(*(const float4*)(Lp0 + segOff), *(const float4*)(Rp0 + segOff));
    float4 aP1 = reluadd4(*(const float4*)(Lp1 + segOff), *(const float4*)(Rp1 + segOff));

    for (int s = 0; s < 48; s++) {
        int cur = s & 1;
        // stage A(s) into As[cur] (rotated k-order: conflict-free STS.32)
        {
            float a0v[4] = {aP0.x, aP0.y, aP0.z, aP0.w};
            float a1v[4] = {aP1.x, aP1.y, aP1.z, aP1.w};
#pragma unroll
            for (int ep = 0; ep < 4; ep++) {
                int e = (ep + seg) & 3;
                As[cur][segOff + e][rowA]      = tf32b(a0v[e]);
                As[cur][segOff + e][rowA + 64] = tf32b(a1v[e]);
            }
        }
        CP_WAIT0();            // B(s) arrived (this thread's copies)
        __syncthreads();       // all threads: A(s)/B(s) visible; s-1 readers done

        if (s < 47) {
            int kn = (s + 1) * 16;
            // B(s+1) -> other buffer (readers of it finished before the barrier)
            uint32_t bd = (cur ? bDst0 : bDst1);
            cp16(bd, WpB + kn);
            cp16(bd + 16, WpB + kn + 4);
            CP_COMMIT();
            // A(s+1) -> regs (overlaps compute)
            aP0 = reluadd4(*(const float4*)(Lp0 + kn + segOff), *(const float4*)(Rp0 + kn + segOff));
            aP1 = reluadd4(*(const float4*)(Lp1 + kn + segOff), *(const float4*)(Rp1 + kn + segOff));
        }

#pragma unroll
        for (int q = 0; q < 2; q++) {
            int kb = q * 8;
            uint32_t bf[8][2];
#pragma unroll
            for (int nt = 0; nt < 8; nt++) {
                int col = wx * 64 + nt * 8 + g;
                bf[nt][0] = Bs[cur][col][kb + tig];
                bf[nt][1] = Bs[cur][col][kb + tig + 4];
            }
#pragma unroll
            for (int m = 0; m < 2; m++) {
                int r0 = wy * 32 + m * 16 + g;
                uint32_t a0 = As[cur][kb + tig][r0];
                uint32_t a1 = As[cur][kb + tig][r0 + 8];
                uint32_t a2 = As[cur][kb + tig + 4][r0];
                uint32_t a3 = As[cur][kb + tig + 4][r0 + 8];
#pragma unroll
                for (int nt = 0; nt < 8; nt++)
                    mma_tf32(acc[m][nt], a0, a1, a2, a3, bf[nt][0], bf[nt][1]);
            }
        }
    }

    // epilogue (R14-proven): +b2, sigmoid, scatter into (65,160,160,4)
#pragma unroll
    for (int m = 0; m < 2; m++) {
        int pa = Mtile * 128 + wy * 32 + m * 16 + g;
        int pb = pa + 8;
        int ia = pa / 160, ja = pa - ia * 160;
        int ib = pb / 160, jb = pb - ib * 160;
#pragma unroll
        for (int nt = 0; nt < 8; nt++) {
            int o = Ntile * 128 + wx * 64 + nt * 8 + tig * 2;
            float bx = b2[o], by = b2[o + 1];
            int rI = o >> 2;
            int off = o & 3;   // 0 or 2
            float2 va, vb;
            va.x = sigf(acc[m][nt][0] + bx);
            va.y = sigf(acc[m][nt][1] + by);
            vb.x = sigf(acc[m][nt][2] + bx);
            vb.y = sigf(acc[m][nt][3] + by);
            *(float2*)&out[((rI * 160 + ia) * 160 + ja) * 4 + off] = va;
            *(float2*)&out[((rI * 160 + ib) * 160 + jb) * 4 + off] = vb;
        }
    }
}

// ---------------------------------------------------------------------------
// Kernel D: tail outputs o = 256..259 (rel index 64).  grid 100, block 256.
// (R10-proven, verbatim.)
// ---------------------------------------------------------------------------
__global__ __launch_bounds__(256) void tail_kernel(const float* __restrict__ W2,
                                                   const float* __restrict__ b2,
                                                   float* __restrict__ out) {
    __shared__ float W2s[4 * H_];
    __shared__ float Ls[3 * H_];

    int t = threadIdx.x;
    int bt = blockIdx.x;             // 0..99
    int p0 = bt * 256;
    int ibase = p0 / 160;

    for (int q = t; q < 4 * H_; q += 256) W2s[q] = W2[256 * H_ + q];
    for (int q = t; q < 3 * H_; q += 256) {
        int r = q / H_;
        int ri = ibase + r; if (ri > 159) ri = 159;
        Ls[q] = g_L[ri * H_ + (q - r * H_)];
    }
    __syncthreads();

    int p = p0 + t;
    int i = p / 160, j = p - i * 160;
    const float4* Rr = (const float4*)(g_R + j * H_);
    const float4* Lr = (const float4*)(Ls + (i - ibase) * H_);
    const float4* w0 = (const float4*)(W2s);
    const float4* w1 = (const float4*)(W2s + H_);
    const float4* w2 = (const float4*)(W2s + 2 * H_);
    const float4* w3 = (const float4*)(W2s + 3 * H_);

    float a0 = 0.f, a1 = 0.f, a2 = 0.f, a3 = 0.f;
#pragma unroll 4
    for (int kk = 0; kk < H_ / 4; kk++) {
        float4 l = Lr[kk];
        float4 r4 = Rr[kk];
        float4 hh = reluadd4(l, r4);
        float4 q0 = w0[kk], q1 = w1[kk], q2 = w2[kk], q3 = w3[kk];
        a0 = fmaf(hh.x, q0.x, fmaf(hh.y, q0.y, fmaf(hh.z, q0.z, fmaf(hh.w, q0.w, a0))));
        a1 = fmaf(hh.x, q1.x, fmaf(hh.y, q1.y, fmaf(hh.z, q1.z, fmaf(hh.w, q1.w, a1))));
        a2 = fmaf(hh.x, q2.x, fmaf(hh.y, q2.y, fmaf(hh.z, q2.z, fmaf(hh.w, q2.w, a2))));
        a3 = fmaf(hh.x, q3.x, fmaf(hh.y, q3.y, fmaf(hh.z, q3.z, fmaf(hh.w, q3.w, a3))));
    }
    float4 o;
    o.x = sigf(a0 + b2[256]);
    o.y = sigf(a1 + b2[257]);
    o.z = sigf(a2 + b2[258]);
    o.w = sigf(a3 + b2[259]);
    *(float4*)&out[((64 * 160 + i) * 160 + j) * 4] = o;
}

// ---------------------------------------------------------------------------
extern "C" void kernel_launch(void* const* d_in, const int* in_sizes, int n_in,
                              void* d_out, int out_size) {
    const float* y  = (const float*)d_in[0];
    // d_in[1] = event_idx (unused by reference)
    const float* W1 = (const float*)d_in[2];
    const float* b1 = (const float*)d_in[3];
    const float* W2 = (const float*)d_in[4];
    const float* b2 = (const float*)d_in[5];
    float* out = (float*)d_out;

    rope_kernel<<<160, 384>>>(y);
    lr_kernel<<<dim3(5, 24), 256>>>(W1, b1);
    tail_kernel<<<100, 256>>>(W2, b2, out);
    main_kernel<<<dim3(200, 2), 256>>>(W2, b2, out);
}

// round 16
// speedup vs baseline: 2.7343x; 1.0449x over previous
#include <cuda_runtime.h>
#include <cstdint>

#define S_ 160
#define H_ 768

// scratch (device globals — no allocation allowed)
__device__ float g_yrot[S_ * H_];
__device__ float g_L[S_ * H_];
__device__ float g_R[S_ * H_];

__device__ __forceinline__ float sigf(float x) { return 1.0f / (1.0f + __expf(-x)); }

__device__ __forceinline__ float4 reluadd4(float4 a, float4 b) {
    float4 r;
    r.x = fmaxf(a.x + b.x, 0.f);
    r.y = fmaxf(a.y + b.y, 0.f);
    r.z = fmaxf(a.z + b.z, 0.f);
    r.w = fmaxf(a.w + b.w, 0.f);
    return r;
}

__device__ __forceinline__ uint32_t tf32b(float x) {
    uint32_t r;
    asm("cvt.rna.tf32.f32 %0, %1;" : "=r"(r) : "f"(x));
    return r;
}

__device__ __forceinline__ uint32_t smem_u32(const void* p) {
    uint32_t a;
    asm("{ .reg .u64 t; cvta.to.shared.u64 t, %1; cvt.u32.u64 %0, t; }" : "=r"(a) : "l"(p));
    return a;
}

__device__ __forceinline__ void cp16(uint32_t dst, const void* src) {
    asm volatile("cp.async.cg.shared.global [%0], [%1], 16;" :: "r"(dst), "l"(src));
}
#define CP_COMMIT() asm volatile("cp.async.commit_group;" ::: "memory")
#define CP_WAIT0()  asm volatile("cp.async.wait_group 0;" ::: "memory")
#define CP_WAIT1()  asm volatile("cp.async.wait_group 1;" ::: "memory")

// D += A(16x8) * B(8x8), tf32 in, fp32 accum.  Canonical m16n8k8 fragments.
__device__ __forceinline__ void mma_tf32(float* c,
                                         uint32_t a0, uint32_t a1, uint32_t a2, uint32_t a3,
                                         uint32_t b0, uint32_t b1) {
    asm volatile(
        "mma.sync.aligned.m16n8k8.row.col.f32.tf32.tf32.f32 "
        "{%0,%1,%2,%3}, {%4,%5,%6,%7}, {%8,%9}, {%0,%1,%2,%3};"
        : "+f"(c[0]), "+f"(c[1]), "+f"(c[2]), "+f"(c[3])
        : "r"(a0), "r"(a1), "r"(a2), "r"(a3), "r"(b0), "r"(b1));
}

// ---------------------------------------------------------------------------
// Kernel A: RoPE.  grid 160, block 384
// ---------------------------------------------------------------------------
__global__ void rope_kernel(const float* __restrict__ y) {
    int s = blockIdx.x;
    int k = threadIdx.x;  // 0..383
    float inv = expf(-(2.0f * (float)k / 768.0f) * 9.210340371976184f);
    float th = (float)s * inv;
    float sn, cs;
    sincosf(th, &sn, &cs);
    float y0 = y[s * H_ + 2 * k];
    float y1 = y[s * H_ + 2 * k + 1];
    g_yrot[s * H_ + 2 * k]     = y0 * cs - y1 * sn;
    g_yrot[s * H_ + 2 * k + 1] = y1 * cs + y0 * sn;
}

// ---------------------------------------------------------------------------
// Kernel B: L/R projections, NOW prefetched + double-buffered (1 barrier/stage).
// BM=32, BN=64, BK=16.  grid (5, 24), 256 threads.
// ---------------------------------------------------------------------------
__global__ __launch_bounds__(256) void lr_kernel(const float* __restrict__ W1,
                                                 const float* __restrict__ b1) {
    __shared__ float As[2][16][34];
    __shared__ float Bs[2][16][68];

    int t = threadIdx.x;
    int Mtile = blockIdx.x;
    int nbase = blockIdx.y * 64;
    int isR = (nbase >= 768);
    int obase = isR ? (nbase - 768) : nbase;
    int cofs = isR ? 768 : 0;
    int tx = t & 15, ty = t >> 4;

    // load mapping
    int rowAq0 = t >> 4, kkA0 = t & 15;          // A elem 0: q = t
    int rowAq1 = (t + 256) >> 4, kkA1 = t & 15;  // A elem 1
    int nnB = t >> 4, kkB = t & 15;              // B elems: nn = t>>4 + it*16

    float acc[2][4];
#pragma unroll
    for (int r = 0; r < 2; r++)
#pragma unroll
        for (int c = 0; c < 4; c++) acc[r][c] = 0.f;

    // prefetch chunk 0
    float aPf[2], bPf[4];
    aPf[0] = g_yrot[(Mtile * 32 + rowAq0) * H_ + kkA0];
    aPf[1] = g_yrot[(Mtile * 32 + rowAq1) * H_ + kkA1];
#pragma unroll
    for (int it = 0; it < 4; it++)
        bPf[it] = W1[(obase + nnB + it * 16) * 1536 + cofs + kkB];

    for (int s = 0; s < 48; s++) {
        int cur = s & 1;
        As[cur][kkA0][rowAq0] = aPf[0];
        As[cur][kkA1][rowAq1] = aPf[1];
#pragma unroll
        for (int it = 0; it < 4; it++)
            Bs[cur][kkB][nnB + it * 16] = bPf[it];
        __syncthreads();

        if (s < 47) {
            int kn = (s + 1) * 16;
            aPf[0] = g_yrot[(Mtile * 32 + rowAq0) * H_ + kn + kkA0];
            aPf[1] = g_yrot[(Mtile * 32 + rowAq1) * H_ + kn + kkA1];
#pragma unroll
            for (int it = 0; it < 4; it++)
                bPf[it] = W1[(obase + nnB + it * 16) * 1536 + cofs + kn + kkB];
        }

#pragma unroll
        for (int kk = 0; kk < 16; kk++) {
            float a0 = As[cur][kk][ty * 2 + 0];
            float a1 = As[cur][kk][ty * 2 + 1];
            float4 b = *(const float4*)&Bs[cur][kk][tx * 4];
            acc[0][0] += a0 * b.x; acc[0][1] += a0 * b.y;
            acc[0][2] += a0 * b.z; acc[0][3] += a0 * b.w;
            acc[1][0] += a1 * b.x; acc[1][1] += a1 * b.y;
            acc[1][2] += a1 * b.z; acc[1][3] += a1 * b.w;
        }
    }

    int s0 = Mtile * 32 + ty * 2;
#pragma unroll
    for (int c = 0; c < 4; c++) {
        int o = obase + tx * 4 + c;
        if (isR) {
            float bb = b1[o];
            g_R[(s0 + 0) * H_ + o] = acc[0][c] + bb;
            g_R[(s0 + 1) * H_ + o] = acc[1][c] + bb;
        } else {
            g_L[(s0 + 0) * H_ + o] = acc[0][c];
            g_L[(s0 + 1) * H_ + o] = acc[1][c];
        }
    }
}

// ---------------------------------------------------------------------------
// Kernel C: main GEMM on tensor cores (mma.sync m16n8k8 tf32).
//   BM=128, BN=128, BK=16, 256 thr, warp tile 32x64, grid (200, 2).
//   A: double-buffered (reg prefetch + cvt + STS).
//   B: THREE-buffer cp.async ring, depth-2 (wait_group 1), raw fp32 bits.
//   One __syncthreads per K-stage.
// ---------------------------------------------------------------------------
__global__ __launch_bounds__(256, 2) void main_kernel(const float* __restrict__ W2,
                                                      const float* __restrict__ b2,
                                                      float* __restrict__ out) {
    __shared__ __align__(16) uint32_t As[2][16][136];   // 17408 B
    __shared__ __align__(16) uint32_t Bs[3][128][20];   // 30720 B

    int t = threadIdx.x;
    int Mtile = blockIdx.x;   // 0..199
    int Ntile = blockIdx.y;   // 0..1
    int lane = t & 31, wid = t >> 5;
    int wy = wid >> 1;        // 0..3 : rows wy*32 .. +31
    int wx = wid & 1;         // 0..1 : cols wx*64 .. +63
    int g = lane >> 2, tig = lane & 3;

    // A staging mapping (proven): rows rowA, rowA+64; k-span segOff..+3
    int rowA = t >> 2;        // 0..63
    int seg = t & 3;
    int segOff = seg * 4;

    int p0 = Mtile * 128 + rowA;
    int p1 = p0 + 64;
    int i0 = p0 / 160, j0 = p0 - i0 * 160;
    int i1 = p1 / 160, j1 = p1 - i1 * 160;
    const float* Lp0 = g_L + i0 * H_;
    const float* Rp0 = g_R + j0 * H_;
    const float* Lp1 = g_L + i1 * H_;
    const float* Rp1 = g_R + j1 * H_;

    // B staging mapping (cp.async): row browB, 8 floats at halfB*8
    int browB = t >> 1;       // 0..127
    int halfB = t & 1;
    const float* WpB = W2 + (Ntile * 128 + browB) * H_ + halfB * 8;
    uint32_t bDst = smem_u32(&Bs[0][browB][halfB * 8]);
    const uint32_t BUFSZ = 128 * 20 * 4;

    float acc[2][8][4];
#pragma unroll
    for (int m = 0; m < 2; m++)
#pragma unroll
        for (int nt = 0; nt < 8; nt++)
#pragma unroll
            for (int c = 0; c < 4; c++) acc[m][nt][c] = 0.f;

    // prologue: B(0), B(1) via cp.async; A(0) into regs
    cp16(bDst, WpB);
    cp16(bDst + 16, WpB + 4);
    CP_COMMIT();
    cp16(bDst + BUFSZ, WpB + 16);
    cp16(bDst + BUFSZ + 16, WpB + 20);
    CP_COMMIT();
    float4 aP0 = reluadd4(*(const float4*)(Lp0 + segOff), *(const float4*)(Rp0 + segOff));
    float4 aP1 = reluadd4(*(const float4*)(Lp1 + segOff), *(const float4*)(Rp1 + segOff));

    int bufB = 0;            // buffer holding B(s)
    for (int s = 0; s < 48; s++) {
        int curA = s & 1;
        // stage A(s) (rotated k-order: conflict-free STS.32)
        {
            float a0v[4] = {aP0.x, aP0.y, aP0.z, aP0.w};
            float a1v[4] = {aP1.x, aP1.y, aP1.z, aP1.w};
#pragma unroll
            for (int ep = 0; ep < 4; ep++) {
                int e = (ep + seg) & 3;
                As[curA][segOff + e][rowA]      = tf32b(a0v[e]);
                As[curA][segOff + e][rowA + 64] = tf32b(a1v[e]);
            }
        }
        if (s < 47) { CP_WAIT1(); } else { CP_WAIT0(); }   // B(s) arrived
        __syncthreads();       // A(s)/B(s) visible to all; s-1 readers done

        if (s < 46) {
            // B(s+2) -> ring buffer (s+2)%3 (its last readers were stage s-1)
            int wb = bufB + 2; if (wb >= 3) wb -= 3;
            uint32_t bd = bDst + (uint32_t)wb * BUFSZ;
            const float* src = WpB + (s + 2) * 16;
            cp16(bd, src);
            cp16(bd + 16, src + 4);
            CP_COMMIT();
        }
        if (s < 47) {
            int kn = (s + 1) * 16;
            aP0 = reluadd4(*(const float4*)(Lp0 + kn + segOff), *(const float4*)(Rp0 + kn + segOff));
            aP1 = reluadd4(*(const float4*)(Lp1 + kn + segOff), *(const float4*)(Rp1 + kn + segOff));
        }

#pragma unroll
        for (int q = 0; q < 2; q++) {
            int kb = q * 8;
            uint32_t bf[8][2];
#pragma unroll
            for (int nt = 0; nt < 8; nt++) {
                int col = wx * 64 + nt * 8 + g;
                bf[nt][0] = Bs[bufB][col][kb + tig];
                bf[nt][1] = Bs[bufB][col][kb + tig + 4];
            }
#pragma unroll
            for (int m = 0; m < 2; m++) {
                int r0 = wy * 32 + m * 16 + g;
                uint32_t a0 = As[curA][kb + tig][r0];
                uint32_t a1 = As[curA][kb + tig][r0 + 8];
                uint32_t a2 = As[curA][kb + tig + 4][r0];
                uint32_t a3 = As[curA][kb + tig + 4][r0 + 8];
#pragma unroll
                for (int nt = 0; nt < 8; nt++)
                    mma_tf32(acc[m][nt], a0, a1, a2, a3, bf[nt][0], bf[nt][1]);
            }
        }
        bufB++; if (bufB >= 3) bufB = 0;
    }

    // epilogue (proven): +b2, sigmoid, scatter into (65,160,160,4)
#pragma unroll
    for (int m = 0; m < 2; m++) {
        int pa = Mtile * 128 + wy * 32 + m * 16 + g;
        int pb = pa + 8;
        int ia = pa / 160, ja = pa - ia * 160;
        int ib = pb / 160, jb = pb - ib * 160;
#pragma unroll
        for (int nt = 0; nt < 8; nt++) {
            int o = Ntile * 128 + wx * 64 + nt * 8 + tig * 2;
            float bx = b2[o], by = b2[o + 1];
            int rI = o >> 2;
            int off = o & 3;   // 0 or 2
            float2 va, vb;
            va.x = sigf(acc[m][nt][0] + bx);
            va.y = sigf(acc[m][nt][1] + by);
            vb.x = sigf(acc[m][nt][2] + bx);
            vb.y = sigf(acc[m][nt][3] + by);
            *(float2*)&out[((rI * 160 + ia) * 160 + ja) * 4 + off] = va;
            *(float2*)&out[((rI * 160 + ib) * 160 + jb) * 4 + off] = vb;
        }
    }
}

// ---------------------------------------------------------------------------
// Kernel D: tail outputs o = 256..259 (rel index 64).  grid 100, block 256.
// (R10-proven, verbatim.)
// ---------------------------------------------------------------------------
__global__ __launch_bounds__(256) void tail_kernel(const float* __restrict__ W2,
                                                   const float* __restrict__ b2,
                                                   float* __restrict__ out) {
    __shared__ float W2s[4 * H_];
    __shared__ float Ls[3 * H_];

    int t = threadIdx.x;
    int bt = blockIdx.x;             // 0..99
    int p0 = bt * 256;
    int ibase = p0 / 160;

    for (int q = t; q < 4 * H_; q += 256) W2s[q] = W2[256 * H_ + q];
    for (int q = t; q < 3 * H_; q += 256) {
        int r = q / H_;
        int ri = ibase + r; if (ri > 159) ri = 159;
        Ls[q] = g_L[ri * H_ + (q - r * H_)];
    }
    __syncthreads();

    int p = p0 + t;
    int i = p / 160, j = p - i * 160;
    const float4* Rr = (const float4*)(g_R + j * H_);
    const float4* Lr = (const float4*)(Ls + (i - ibase) * H_);
    const float4* w0 = (const float4*)(W2s);
    const float4* w1 = (const float4*)(W2s + H_);
    const float4* w2 = (const float4*)(W2s + 2 * H_);
    const float4* w3 = (const float4*)(W2s + 3 * H_);

    float a0 = 0.f, a1 = 0.f, a2 = 0.f, a3 = 0.f;
#pragma unroll 4
    for (int kk = 0; kk < H_ / 4; kk++) {
        float4 l = Lr[kk];
        float4 r4 = Rr[kk];
        float4 hh = reluadd4(l, r4);
        float4 q0 = w0[kk], q1 = w1[kk], q2 = w2[kk], q3 = w3[kk];
        a0 = fmaf(hh.x, q0.x, fmaf(hh.y, q0.y, fmaf(hh.z, q0.z, fmaf(hh.w, q0.w, a0))));
        a1 = fmaf(hh.x, q1.x, fmaf(hh.y, q1.y, fmaf(hh.z, q1.z, fmaf(hh.w, q1.w, a1))));
        a2 = fmaf(hh.x, q2.x, fmaf(hh.y, q2.y, fmaf(hh.z, q2.z, fmaf(hh.w, q2.w, a2))));
        a3 = fmaf(hh.x, q3.x, fmaf(hh.y, q3.y, fmaf(hh.z, q3.z, fmaf(hh.w, q3.w, a3))));
    }
    float4 o;
    o.x = sigf(a0 + b2[256]);
    o.y = sigf(a1 + b2[257]);
    o.z = sigf(a2 + b2[258]);
    o.w = sigf(a3 + b2[259]);
    *(float4*)&out[((64 * 160 + i) * 160 + j) * 4] = o;
}

// ---------------------------------------------------------------------------
extern "C" void kernel_launch(void* const* d_in, const int* in_sizes, int n_in,
                              void* d_out, int out_size) {
    const float* y  = (const float*)d_in[0];
    // d_in[1] = event_idx (unused by reference)
    const float* W1 = (const float*)d_in[2];
    const float* b1 = (const float*)d_in[3];
    const float* W2 = (const float*)d_in[4];
    const float* b2 = (const float*)d_in[5];
    float* out = (float*)d_out;

    rope_kernel<<<160, 384>>>(y);
    lr_kernel<<<dim3(5, 24), 256>>>(W1, b1);
    tail_kernel<<<100, 256>>>(W2, b2, out);
    main_kernel<<<dim3(200, 2), 256>>>(W2, b2, out);
}